// round 5
// baseline (speedup 1.0000x reference)
#include <cuda_runtime.h>
#include <cuda_bf16.h>
#include <cstdint>
#include <cstddef>

#define T_STEPS 8192
#define HIDN    1024
#define G3      3072
#define NCTA    128
#define GRU_THREADS 512
#define SMEM_BYTES 100480   // 98304 (Wh slice) + 2048 (red) + 128 (bh)

__device__ float g_gi[(size_t)T_STEPS * G3];
__device__ float g_ys[(size_t)T_STEPS * HIDN];
__device__ unsigned g_bar_cnt;
__device__ unsigned g_bar_gen;

__global__ void reset_bar_kernel() { g_bar_cnt = 0u; g_bar_gen = 0u; }

// ---------------- Phase 1: gi = x @ Wi --------------------------------------
__global__ __launch_bounds__(256)
void sgemm_kernel(const float* __restrict__ A, const float* __restrict__ B)
{
    const int N = G3, K = HIDN;
    __shared__ float As[16][128];
    __shared__ float Bs[16][128];
    const int tid = threadIdx.x, bx = blockIdx.x, by = blockIdx.y;
    const float* Ab = A + (size_t)by * 128 * K;
    const float* Bb = B + (size_t)bx * 128;
    float* Cb = g_gi + (size_t)by * 128 * N + (size_t)bx * 128;
    const int tcol = tid & 15, trow = tid >> 4;
    const int aRow = tid >> 2, aCol = (tid & 3) * 4;
    const int bRow = tid >> 5, bCol = (tid & 31) * 4;
    float acc[8][8];
#pragma unroll
    for (int i = 0; i < 8; i++)
#pragma unroll
        for (int j = 0; j < 8; j++) acc[i][j] = 0.f;
    float regM[8], regN[8];
    for (int k0 = 0; k0 < K; k0 += 16) {
#pragma unroll
        for (int i = 0; i < 2; i++) {
            float4 v = *reinterpret_cast<const float4*>(Ab + (size_t)(aRow + 64 * i) * K + k0 + aCol);
            As[aCol + 0][aRow + 64 * i] = v.x; As[aCol + 1][aRow + 64 * i] = v.y;
            As[aCol + 2][aRow + 64 * i] = v.z; As[aCol + 3][aRow + 64 * i] = v.w;
        }
#pragma unroll
        for (int i = 0; i < 2; i++) {
            float4 v = *reinterpret_cast<const float4*>(Bb + (size_t)(k0 + bRow + 8 * i) * N + bCol);
            *reinterpret_cast<float4*>(&Bs[bRow + 8 * i][bCol]) = v;
        }
        __syncthreads();
#pragma unroll
        for (int k = 0; k < 16; k++) {
#pragma unroll
            for (int i = 0; i < 8; i += 4)
                *reinterpret_cast<float4*>(&regM[i]) = *reinterpret_cast<float4*>(&As[k][trow * 8 + i]);
#pragma unroll
            for (int i = 0; i < 8; i += 4)
                *reinterpret_cast<float4*>(&regN[i]) = *reinterpret_cast<float4*>(&Bs[k][tcol * 8 + i]);
#pragma unroll
            for (int i = 0; i < 8; i++)
#pragma unroll
                for (int j = 0; j < 8; j++) acc[i][j] = fmaf(regM[i], regN[j], acc[i][j]);
        }
        __syncthreads();
    }
#pragma unroll
    for (int i = 0; i < 8; i++)
#pragma unroll
        for (int j = 0; j < 8; j += 4)
            *reinterpret_cast<float4*>(Cb + (size_t)(trow * 8 + i) * N + tcol * 8 + j) =
                *reinterpret_cast<const float4*>(&acc[i][j]);
}

// ---------------- Phase 2: persistent GRU recurrence ------------------------
__device__ __forceinline__ int colmap(int j, int u0) {
    return (j >> 3) * HIDN + u0 + (j & 7);   // j: 0-7 r, 8-15 z, 16-23 n
}

__global__ __launch_bounds__(GRU_THREADS, 1)
void gru_kernel(const float* __restrict__ h0, const float* __restrict__ Wh,
                const float* __restrict__ bh)
{
    extern __shared__ float smem[];
    float4* ws4 = reinterpret_cast<float4*>(smem);       // [256 kgrp][24] f4
    float* red  = smem + 24576;                          // 16*32
    float* bh_s = smem + 24576 + 512;                    // 32
    const int tid = threadIdx.x, lane = tid & 31, warp = tid >> 5;
    const int u0 = blockIdx.x * 8;

    for (int idx = tid; idx < HIDN * 24; idx += GRU_THREADS) {
        int k = idx / 24, j = idx - k * 24;
        smem[(((k >> 2) * 24) + j) * 4 + (k & 3)] = Wh[(size_t)k * G3 + colmap(j, u0)];
    }
    if (tid < 32) bh_s[tid] = (tid < 24) ? bh[colmap(tid, u0)] : 0.f;
    __syncthreads();

    const int col = (lane < 24) ? colmap(lane, u0) : 0;
    const float4* wsw = ws4 + warp * 16 * 24;

    for (int t = 0; t < T_STEPS; ++t) {
        const float* hsrc = (t == 0) ? h0 : (g_ys + (size_t)(t - 1) * HIDN);
        float4 hv = make_float4(0.f, 0.f, 0.f, 0.f);
        if (lane < 16)
            hv = __ldcg(reinterpret_cast<const float4*>(hsrc) + warp * 16 + lane);
        float giv = 0.f, hold = 0.f;
        if (warp == 0) {
            if (lane < 24) giv = __ldcg(g_gi + (size_t)t * G3 + col);
            if (lane < 8)  hold = __ldcg(hsrc + u0 + lane);
        }
        float acc = 0.f;
#pragma unroll
        for (int g = 0; g < 16; ++g) {
            float hx = __shfl_sync(0xffffffffu, hv.x, g);
            float hy = __shfl_sync(0xffffffffu, hv.y, g);
            float hz = __shfl_sync(0xffffffffu, hv.z, g);
            float hw = __shfl_sync(0xffffffffu, hv.w, g);
            if (lane < 24) {
                float4 w = wsw[g * 24 + lane];
                acc = fmaf(w.x, hx, acc); acc = fmaf(w.y, hy, acc);
                acc = fmaf(w.z, hz, acc); acc = fmaf(w.w, hw, acc);
            }
        }
        red[warp * 32 + lane] = acc;
        __syncthreads();
        if (warp == 0) {
            float s = bh_s[lane];
#pragma unroll
            for (int w = 0; w < 16; ++w) s += red[w * 32 + lane];
            float gh = s, gi = giv;
            float gh_z = __shfl_sync(0xffffffffu, gh, (lane + 8) & 31);
            float gi_z = __shfl_sync(0xffffffffu, gi, (lane + 8) & 31);
            float gh_n = __shfl_sync(0xffffffffu, gh, (lane + 16) & 31);
            float gi_n = __shfl_sync(0xffffffffu, gi, (lane + 16) & 31);
            if (lane < 8) {
                float r = 0.5f + 0.5f * tanhf(0.5f * (gi + gh));
                float z = 0.5f + 0.5f * tanhf(0.5f * (gi_z + gh_z));
                float n = tanhf(fmaf(r, gh_n, gi_n));
                g_ys[(size_t)t * HIDN + u0 + lane] = fmaf(z, hold - n, n);
            }
            __threadfence();
            if (lane == 0) {
                const unsigned target = (unsigned)t + 1u;
                unsigned a = atomicAdd(&g_bar_cnt, 1u);
                if (a == NCTA - 1u) {
                    atomicExch(&g_bar_cnt, 0u);
                    __threadfence();
                    atomicExch(&g_bar_gen, target);
                } else {
                    while (*((volatile unsigned*)&g_bar_gen) < target) { }
                }
            }
        }
        __syncthreads();
    }
}

// ---------------- Phase 3: logits = ys @ Wd + bd ----------------------------
__global__ __launch_bounds__(256)
void dense_kernel(const float* __restrict__ Wd, const float* __restrict__ bd,
                  float* __restrict__ out, int out_size)
{
    __shared__ float wd_s[HIDN * 9];
    const int tid = threadIdx.x;
    for (int i = tid; i < HIDN * 8; i += 256) wd_s[(i >> 3) * 9 + (i & 7)] = Wd[i];
    __syncthreads();
    const int warp = tid >> 5, lane = tid & 31;
    const int t = blockIdx.x * 8 + warp;
    const float* yrow = g_ys + (size_t)t * HIDN;
    float acc[8];
#pragma unroll
    for (int o = 0; o < 8; o++) acc[o] = 0.f;
#pragma unroll 4
    for (int i = 0; i < 32; i++) {
        int u = i * 32 + lane;
        float y = __ldg(yrow + u);
#pragma unroll
        for (int o = 0; o < 8; o++) acc[o] = fmaf(y, wd_s[u * 9 + o], acc[o]);
    }
#pragma unroll
    for (int o = 0; o < 8; o++) {
        float v = acc[o];
#pragma unroll
        for (int off = 16; off; off >>= 1) v += __shfl_xor_sync(0xffffffffu, v, off);
        int oi = t * 8 + o;
        if (lane == 0 && oi < out_size) out[oi] = v + bd[o];
    }
}

// ---------------- Phase 4: threefry2x32 (PARTITIONABLE path) ----------------
__device__ __forceinline__ void tf2x32(unsigned k0, unsigned k1,
                                       unsigned x0, unsigned x1,
                                       unsigned& o0, unsigned& o1)
{
    unsigned k2 = k0 ^ k1 ^ 0x1BD11BDAu;
    x0 += k0; x1 += k1;
#define RND(r) x0 += x1; x1 = (x1 << (r)) | (x1 >> (32 - (r))); x1 ^= x0;
    RND(13) RND(15) RND(26) RND(6)
    x0 += k1; x1 += k2 + 1u;
    RND(17) RND(29) RND(16) RND(24)
    x0 += k2; x1 += k0 + 2u;
    RND(13) RND(15) RND(26) RND(6)
    x0 += k0; x1 += k1 + 3u;
    RND(17) RND(29) RND(16) RND(24)
    x0 += k1; x1 += k2 + 4u;
    RND(13) RND(15) RND(26) RND(6)
    x0 += k2; x1 += k0 + 5u;
#undef RND
    o0 = x0; o1 = x1;
}

__device__ __forceinline__ float gumbel_bits(unsigned b)
{
    float u = __uint_as_float((b >> 9) | 0x3f800000u) - 1.0f;
    u = fmaxf(u, 1.17549435e-38f);
    return -logf(-logf(u));
}

__global__ void action_kernel(const int* __restrict__ seedp,
                              float* __restrict__ out, int out_size)
{
    const int t = blockIdx.x * 256 + threadIdx.x;
    const unsigned sk0 = 0u, sk1 = (unsigned)seedp[0];
    // jax_threefry_partitionable split: key_i = tf(key, (hi=0, lo=i));
    // act_rng = split(rng)[1] = tf(key, (0, 1)) -> full (o0, o1) pair.
    unsigned ak0, ak1;
    tf2x32(sk0, sk1, 0u, 1u, ak0, ak1);
    // partitionable random_bits(32, shape=(8192,2)): flat 64-bit iota index i,
    // (b1,b2) = tf(act_key, (hi(i)=0, lo(i)=i)); bits = b1 ^ b2.
    const unsigned i0 = 2u * (unsigned)t, i1 = i0 + 1u;
    unsigned b1, b2, c1, c2;
    tf2x32(ak0, ak1, 0u, i0, b1, b2);
    tf2x32(ak0, ak1, 0u, i1, c1, c2);
    const float s0 = gumbel_bits(b1 ^ b2) + out[(size_t)t * 8 + 0];
    const float s1 = gumbel_bits(c1 ^ c2) + out[(size_t)t * 8 + 1];
    int oi = 65536 + t;
    if (oi < out_size) out[oi] = (s1 > s0) ? 1.0f : 0.0f;   // argmax, first-index ties
}

__global__ void finalh_kernel(float* __restrict__ out, int out_size)
{
    int i = threadIdx.x;                     // 1024 threads
    int oi = 65536 + 8192 + i;
    if (oi < out_size) out[oi] = g_ys[(size_t)(T_STEPS - 1) * HIDN + i];
}

// ---------------------------------------------------------------------------
extern "C" void kernel_launch(void* const* d_in, const int* in_sizes, int n_in,
                              void* d_out, int out_size)
{
    const float* x  = (const float*)d_in[0];
    const float* h0 = (const float*)d_in[1];
    const float* Wi = (const float*)d_in[2];
    const float* Wh = (const float*)d_in[3];
    const float* bh = (const float*)d_in[4];
    const float* Wd = (const float*)d_in[5];
    const float* bd = (const float*)d_in[6];
    const int* seed = (const int*)d_in[7];
    float* out = (float*)d_out;

    cudaFuncSetAttribute(gru_kernel, cudaFuncAttributeMaxDynamicSharedMemorySize, SMEM_BYTES);

    sgemm_kernel<<<dim3(24, 64), 256>>>(x, Wi);
    reset_bar_kernel<<<1, 1>>>();
    gru_kernel<<<NCTA, GRU_THREADS, SMEM_BYTES>>>(h0, Wh, bh);
    dense_kernel<<<1024, 256>>>(Wd, bd, out, out_size);
    if (out_size > 65536) action_kernel<<<32, 256>>>(seed, out, out_size);
    if (out_size > 65536 + 8192) finalh_kernel<<<1, 1024>>>(out, out_size);
}

// round 7
// speedup vs baseline: 1.0778x; 1.0778x over previous
#include <cuda_runtime.h>
#include <cuda_bf16.h>
#include <cstdint>
#include <cstddef>

#define T_STEPS 8192
#define HIDN    1024
#define G3      3072
#define NCTA    128
#define GRU_THREADS 768   // 24 warps: one per gate column of the CTA's 8 units

__device__ float g_gi[(size_t)T_STEPS * G3];
__device__ float g_ys[(size_t)T_STEPS * HIDN];
__device__ unsigned g_flag[NCTA * 32];   // one flag per CTA, 128B apart

__global__ void reset_flags_kernel() {
    int i = blockIdx.x * 256 + threadIdx.x;
    if (i < NCTA * 32) g_flag[i] = 0u;
}

// ---------------- Phase 1: gi = x @ Wi (unchanged, verified) ----------------
__global__ __launch_bounds__(256)
void sgemm_kernel(const float* __restrict__ A, const float* __restrict__ B)
{
    const int N = G3, K = HIDN;
    __shared__ float As[16][128];
    __shared__ float Bs[16][128];
    const int tid = threadIdx.x, bx = blockIdx.x, by = blockIdx.y;
    const float* Ab = A + (size_t)by * 128 * K;
    const float* Bb = B + (size_t)bx * 128;
    float* Cb = g_gi + (size_t)by * 128 * N + (size_t)bx * 128;
    const int tcol = tid & 15, trow = tid >> 4;
    const int aRow = tid >> 2, aCol = (tid & 3) * 4;
    const int bRow = tid >> 5, bCol = (tid & 31) * 4;
    float acc[8][8];
#pragma unroll
    for (int i = 0; i < 8; i++)
#pragma unroll
        for (int j = 0; j < 8; j++) acc[i][j] = 0.f;
    float regM[8], regN[8];
    for (int k0 = 0; k0 < K; k0 += 16) {
#pragma unroll
        for (int i = 0; i < 2; i++) {
            float4 v = *reinterpret_cast<const float4*>(Ab + (size_t)(aRow + 64 * i) * K + k0 + aCol);
            As[aCol + 0][aRow + 64 * i] = v.x; As[aCol + 1][aRow + 64 * i] = v.y;
            As[aCol + 2][aRow + 64 * i] = v.z; As[aCol + 3][aRow + 64 * i] = v.w;
        }
#pragma unroll
        for (int i = 0; i < 2; i++) {
            float4 v = *reinterpret_cast<const float4*>(Bb + (size_t)(k0 + bRow + 8 * i) * N + bCol);
            *reinterpret_cast<float4*>(&Bs[bRow + 8 * i][bCol]) = v;
        }
        __syncthreads();
#pragma unroll
        for (int k = 0; k < 16; k++) {
#pragma unroll
            for (int i = 0; i < 8; i += 4)
                *reinterpret_cast<float4*>(&regM[i]) = *reinterpret_cast<float4*>(&As[k][trow * 8 + i]);
#pragma unroll
            for (int i = 0; i < 8; i += 4)
                *reinterpret_cast<float4*>(&regN[i]) = *reinterpret_cast<float4*>(&Bs[k][tcol * 8 + i]);
#pragma unroll
            for (int i = 0; i < 8; i++)
#pragma unroll
                for (int j = 0; j < 8; j++) acc[i][j] = fmaf(regM[i], regN[j], acc[i][j]);
        }
        __syncthreads();
    }
#pragma unroll
    for (int i = 0; i < 8; i++)
#pragma unroll
        for (int j = 0; j < 8; j += 4)
            *reinterpret_cast<float4*>(Cb + (size_t)(trow * 8 + i) * N + tcol * 8 + j) =
                *reinterpret_cast<const float4*>(&acc[i][j]);
}

// ---------------- Phase 2: persistent GRU, register weights + flag sync -----
__global__ __launch_bounds__(GRU_THREADS, 1)
void gru_kernel(const float* __restrict__ h0, const float* __restrict__ Wh,
                const float* __restrict__ bh)
{
    __shared__ float colsum[32];
    const int tid  = threadIdx.x;
    const int lane = tid & 31;
    const int warp = tid >> 5;            // 0..23, owns one gate column
    const int u0   = blockIdx.x * 8;
    const int colw = (warp >> 3) * HIDN + u0 + (warp & 7);   // [r|z|n] order

    // one-time: weights + bias into registers
    float wreg[32];
#pragma unroll
    for (int i = 0; i < 32; i++)
        wreg[i] = Wh[(size_t)(i * 32 + lane) * G3 + colw];
    const float bhv = bh[colw];

    // own hidden state (warp 0, lanes 0-7)
    float hown = 0.f;
    if (warp == 0 && lane < 8) hown = h0[u0 + lane];

    unsigned* const myflag = g_flag + blockIdx.x * 32;
    const unsigned* const pollp = g_flag + (tid < NCTA ? tid : 0) * 32;

    for (int t = 0; t < T_STEPS; ++t) {
        // prefetch gi for this step (independent of recurrence)
        float giv = 0.f;
        if (warp == 0 && lane < 24) {
            int cg = (lane >> 3) * HIDN + u0 + (lane & 7);
            giv = __ldg(g_gi + (size_t)t * G3 + cg);
        }

        const float* hsrc;
        if (t == 0) {
            hsrc = h0;
        } else {
            hsrc = g_ys + (size_t)(t - 1) * HIDN;
            if (tid < NCTA) {
                unsigned v;
                do {
                    asm volatile("ld.acquire.gpu.u32 %0, [%1];"
                                 : "=r"(v) : "l"(pollp) : "memory");
                } while (v < (unsigned)t);
            }
            __syncthreads();   // propagate acquire CTA-wide
        }

        // matvec: this warp's column, 4-way ILP
        float a0 = 0.f, a1 = 0.f, a2 = 0.f, a3 = 0.f;
#pragma unroll
        for (int i = 0; i < 32; i += 4) {
            float h0v = hsrc[(i + 0) * 32 + lane];
            float h1v = hsrc[(i + 1) * 32 + lane];
            float h2v = hsrc[(i + 2) * 32 + lane];
            float h3v = hsrc[(i + 3) * 32 + lane];
            a0 = fmaf(wreg[i + 0], h0v, a0);
            a1 = fmaf(wreg[i + 1], h1v, a1);
            a2 = fmaf(wreg[i + 2], h2v, a2);
            a3 = fmaf(wreg[i + 3], h3v, a3);
        }
        float s = (a0 + a1) + (a2 + a3);
#pragma unroll
        for (int off = 16; off; off >>= 1)
            s += __shfl_xor_sync(0xffffffffu, s, off);
        if (lane == 0) colsum[warp] = s + bhv;
        __syncthreads();

        // tail: warp 0 computes the 8 new h values
        if (warp == 0) {
            float gh = (lane < 24) ? colsum[lane] : 0.f;
            float gi = giv;
            float gh_z = __shfl_sync(0xffffffffu, gh, (lane + 8) & 31);
            float gi_z = __shfl_sync(0xffffffffu, gi, (lane + 8) & 31);
            float gh_n = __shfl_sync(0xffffffffu, gh, (lane + 16) & 31);
            float gi_n = __shfl_sync(0xffffffffu, gi, (lane + 16) & 31);
            if (lane < 8) {
                float r = 0.5f + 0.5f * tanhf(0.5f * (gi + gh));
                float z = 0.5f + 0.5f * tanhf(0.5f * (gi_z + gh_z));
                float n = tanhf(fmaf(r, gh_n, gi_n));
                float hn = fmaf(z, hown - n, n);
                hown = hn;
                g_ys[(size_t)t * HIDN + u0 + lane] = hn;
            }
            __threadfence();
            __syncwarp();
            if (lane == 0)
                asm volatile("st.release.gpu.u32 [%0], %1;"
                             :: "l"(myflag), "r"((unsigned)(t + 1)) : "memory");
        }
        // no trailing bar: warps re-block at next step's flag wait (own flag
        // only advances after warp 0 has consumed colsum) -> no WAR hazard.
    }
}

// ---------------- Phase 3: logits = ys @ Wd + bd (unchanged) ----------------
__global__ __launch_bounds__(256)
void dense_kernel(const float* __restrict__ Wd, const float* __restrict__ bd,
                  float* __restrict__ out, int out_size)
{
    __shared__ float wd_s[HIDN * 9];
    const int tid = threadIdx.x;
    for (int i = tid; i < HIDN * 8; i += 256) wd_s[(i >> 3) * 9 + (i & 7)] = Wd[i];
    __syncthreads();
    const int warp = tid >> 5, lane = tid & 31;
    const int t = blockIdx.x * 8 + warp;
    const float* yrow = g_ys + (size_t)t * HIDN;
    float acc[8];
#pragma unroll
    for (int o = 0; o < 8; o++) acc[o] = 0.f;
#pragma unroll 4
    for (int i = 0; i < 32; i++) {
        int u = i * 32 + lane;
        float y = __ldg(yrow + u);
#pragma unroll
        for (int o = 0; o < 8; o++) acc[o] = fmaf(y, wd_s[u * 9 + o], acc[o]);
    }
#pragma unroll
    for (int o = 0; o < 8; o++) {
        float v = acc[o];
#pragma unroll
        for (int off = 16; off; off >>= 1) v += __shfl_xor_sync(0xffffffffu, v, off);
        int oi = t * 8 + o;
        if (lane == 0 && oi < out_size) out[oi] = v + bd[o];
    }
}

// ---------------- Phase 4: threefry (partitionable, verified) ---------------
__device__ __forceinline__ void tf2x32(unsigned k0, unsigned k1,
                                       unsigned x0, unsigned x1,
                                       unsigned& o0, unsigned& o1)
{
    unsigned k2 = k0 ^ k1 ^ 0x1BD11BDAu;
    x0 += k0; x1 += k1;
#define RND(r) x0 += x1; x1 = (x1 << (r)) | (x1 >> (32 - (r))); x1 ^= x0;
    RND(13) RND(15) RND(26) RND(6)
    x0 += k1; x1 += k2 + 1u;
    RND(17) RND(29) RND(16) RND(24)
    x0 += k2; x1 += k0 + 2u;
    RND(13) RND(15) RND(26) RND(6)
    x0 += k0; x1 += k1 + 3u;
    RND(17) RND(29) RND(16) RND(24)
    x0 += k1; x1 += k2 + 4u;
    RND(13) RND(15) RND(26) RND(6)
    x0 += k2; x1 += k0 + 5u;
#undef RND
    o0 = x0; o1 = x1;
}

__device__ __forceinline__ float gumbel_bits(unsigned b)
{
    float u = __uint_as_float((b >> 9) | 0x3f800000u) - 1.0f;
    u = fmaxf(u, 1.17549435e-38f);
    return -logf(-logf(u));
}

__global__ void action_kernel(const int* __restrict__ seedp,
                              float* __restrict__ out, int out_size)
{
    const int t = blockIdx.x * 256 + threadIdx.x;
    const unsigned sk0 = 0u, sk1 = (unsigned)seedp[0];
    unsigned ak0, ak1;
    tf2x32(sk0, sk1, 0u, 1u, ak0, ak1);          // act_rng = split(rng)[1]
    const unsigned i0 = 2u * (unsigned)t, i1 = i0 + 1u;
    unsigned b1, b2, c1, c2;
    tf2x32(ak0, ak1, 0u, i0, b1, b2);
    tf2x32(ak0, ak1, 0u, i1, c1, c2);
    const float s0 = gumbel_bits(b1 ^ b2) + out[(size_t)t * 8 + 0];
    const float s1 = gumbel_bits(c1 ^ c2) + out[(size_t)t * 8 + 1];
    int oi = 65536 + t;
    if (oi < out_size) out[oi] = (s1 > s0) ? 1.0f : 0.0f;
}

__global__ void finalh_kernel(float* __restrict__ out, int out_size)
{
    int i = threadIdx.x;
    int oi = 65536 + 8192 + i;
    if (oi < out_size) out[oi] = g_ys[(size_t)(T_STEPS - 1) * HIDN + i];
}

// ---------------------------------------------------------------------------
extern "C" void kernel_launch(void* const* d_in, const int* in_sizes, int n_in,
                              void* d_out, int out_size)
{
    const float* x  = (const float*)d_in[0];
    const float* h0 = (const float*)d_in[1];
    const float* Wi = (const float*)d_in[2];
    const float* Wh = (const float*)d_in[3];
    const float* bh = (const float*)d_in[4];
    const float* Wd = (const float*)d_in[5];
    const float* bd = (const float*)d_in[6];
    const int* seed = (const int*)d_in[7];
    float* out = (float*)d_out;

    reset_flags_kernel<<<16, 256>>>();
    sgemm_kernel<<<dim3(24, 64), 256>>>(x, Wi);
    gru_kernel<<<NCTA, GRU_THREADS>>>(h0, Wh, bh);
    dense_kernel<<<1024, 256>>>(Wd, bd, out, out_size);
    if (out_size > 65536) action_kernel<<<32, 256>>>(seed, out, out_size);
    if (out_size > 65536 + 8192) finalh_kernel<<<1, 1024>>>(out, out_size);
}

// round 8
// speedup vs baseline: 1.3203x; 1.2249x over previous
#include <cuda_runtime.h>
#include <cuda_bf16.h>
#include <cstdint>
#include <cstddef>

#define T_STEPS 8192
#define HIDN    1024
#define G3      3072
#define NCTA    128
#define GRU_THREADS 256   // 8 warps: one per hidden unit of the CTA's 8 units

__device__ float g_gi[(size_t)T_STEPS * G3];
__device__ float g_ys[(size_t)T_STEPS * HIDN];
__device__ unsigned g_flag[NCTA * 32];   // one flag per CTA, 128B apart

__global__ void reset_flags_kernel() {
    int i = blockIdx.x * 256 + threadIdx.x;
    if (i < NCTA * 32) g_flag[i] = 0u;
}

// ---------------- Phase 1: gi = x @ Wi (unchanged, verified) ----------------
__global__ __launch_bounds__(256)
void sgemm_kernel(const float* __restrict__ A, const float* __restrict__ B)
{
    const int N = G3, K = HIDN;
    __shared__ float As[16][128];
    __shared__ float Bs[16][128];
    const int tid = threadIdx.x, bx = blockIdx.x, by = blockIdx.y;
    const float* Ab = A + (size_t)by * 128 * K;
    const float* Bb = B + (size_t)bx * 128;
    float* Cb = g_gi + (size_t)by * 128 * N + (size_t)bx * 128;
    const int tcol = tid & 15, trow = tid >> 4;
    const int aRow = tid >> 2, aCol = (tid & 3) * 4;
    const int bRow = tid >> 5, bCol = (tid & 31) * 4;
    float acc[8][8];
#pragma unroll
    for (int i = 0; i < 8; i++)
#pragma unroll
        for (int j = 0; j < 8; j++) acc[i][j] = 0.f;
    float regM[8], regN[8];
    for (int k0 = 0; k0 < K; k0 += 16) {
#pragma unroll
        for (int i = 0; i < 2; i++) {
            float4 v = *reinterpret_cast<const float4*>(Ab + (size_t)(aRow + 64 * i) * K + k0 + aCol);
            As[aCol + 0][aRow + 64 * i] = v.x; As[aCol + 1][aRow + 64 * i] = v.y;
            As[aCol + 2][aRow + 64 * i] = v.z; As[aCol + 3][aRow + 64 * i] = v.w;
        }
#pragma unroll
        for (int i = 0; i < 2; i++) {
            float4 v = *reinterpret_cast<const float4*>(Bb + (size_t)(k0 + bRow + 8 * i) * N + bCol);
            *reinterpret_cast<float4*>(&Bs[bRow + 8 * i][bCol]) = v;
        }
        __syncthreads();
#pragma unroll
        for (int k = 0; k < 16; k++) {
#pragma unroll
            for (int i = 0; i < 8; i += 4)
                *reinterpret_cast<float4*>(&regM[i]) = *reinterpret_cast<float4*>(&As[k][trow * 8 + i]);
#pragma unroll
            for (int i = 0; i < 8; i += 4)
                *reinterpret_cast<float4*>(&regN[i]) = *reinterpret_cast<float4*>(&Bs[k][tcol * 8 + i]);
#pragma unroll
            for (int i = 0; i < 8; i++)
#pragma unroll
                for (int j = 0; j < 8; j++) acc[i][j] = fmaf(regM[i], regN[j], acc[i][j]);
        }
        __syncthreads();
    }
#pragma unroll
    for (int i = 0; i < 8; i++)
#pragma unroll
        for (int j = 0; j < 8; j += 4)
            *reinterpret_cast<float4*>(Cb + (size_t)(trow * 8 + i) * N + tcol * 8 + j) =
                *reinterpret_cast<const float4*>(&acc[i][j]);
}

// ---------------- Phase 2: GRU — warp-per-unit, 3 gates in-warp -------------
__global__ __launch_bounds__(GRU_THREADS, 1)
void gru_kernel(const float* __restrict__ h0, const float* __restrict__ Wh,
                const float* __restrict__ bh)
{
    const int tid  = threadIdx.x;
    const int lane = tid & 31;
    const int warp = tid >> 5;                 // 0..7 = this CTA's hidden unit
    const int uu   = blockIdx.x * 8 + warp;    // global unit index

    // one-time: per-gate weight columns into registers (k = i*32 + lane)
    float wr[32], wz[32], wn[32];
#pragma unroll
    for (int i = 0; i < 32; i++) {
        size_t krow = (size_t)(i * 32 + lane) * G3;
        wr[i] = Wh[krow + uu];
        wz[i] = Wh[krow + HIDN + uu];
        wn[i] = Wh[krow + 2 * HIDN + uu];
    }
    // biases, broadcast to all lanes
    float bt = (lane < 3) ? bh[lane * HIDN + uu] : 0.f;
    const float br = __shfl_sync(0xffffffffu, bt, 0);
    const float bz = __shfl_sync(0xffffffffu, bt, 1);
    const float bn = __shfl_sync(0xffffffffu, bt, 2);

    float hprev = h0[uu];   // every lane tracks own unit's h (lane0 authoritative)

    unsigned* const myflag = g_flag + blockIdx.x * 32;
    const unsigned* const pollp = g_flag + (tid < NCTA ? tid : 0) * 32;

    for (int t = 0; t < T_STEPS; ++t) {
        // gi prefetch (independent of recurrence) — lanes 0..2 = r,z,n
        float giv = 0.f;
        if (lane < 3) giv = __ldg(g_gi + (size_t)t * G3 + lane * HIDN + uu);

        const float* hsrc;
        if (t == 0) {
            hsrc = h0;
        } else {
            hsrc = g_ys + (size_t)(t - 1) * HIDN;
            if (tid < NCTA) {
                unsigned v;
                do {
                    asm volatile("ld.relaxed.gpu.u32 %0, [%1];"
                                 : "=r"(v) : "l"(pollp) : "memory");
                } while (v < (unsigned)t);
                asm volatile("fence.acq_rel.gpu;" ::: "memory");
            }
            __syncthreads();   // propagate acquire CTA-wide
        }

        // matvec for 3 gate columns, 12 accumulators
        float ar0 = 0.f, ar1 = 0.f, ar2 = 0.f, ar3 = 0.f;
        float az0 = 0.f, az1 = 0.f, az2 = 0.f, az3 = 0.f;
        float an0 = 0.f, an1 = 0.f, an2 = 0.f, an3 = 0.f;
#pragma unroll
        for (int i = 0; i < 32; i += 4) {
            float h0v = hsrc[(i + 0) * 32 + lane];
            float h1v = hsrc[(i + 1) * 32 + lane];
            float h2v = hsrc[(i + 2) * 32 + lane];
            float h3v = hsrc[(i + 3) * 32 + lane];
            ar0 = fmaf(wr[i + 0], h0v, ar0); az0 = fmaf(wz[i + 0], h0v, az0); an0 = fmaf(wn[i + 0], h0v, an0);
            ar1 = fmaf(wr[i + 1], h1v, ar1); az1 = fmaf(wz[i + 1], h1v, az1); an1 = fmaf(wn[i + 1], h1v, an1);
            ar2 = fmaf(wr[i + 2], h2v, ar2); az2 = fmaf(wz[i + 2], h2v, az2); an2 = fmaf(wn[i + 2], h2v, an2);
            ar3 = fmaf(wr[i + 3], h3v, ar3); az3 = fmaf(wz[i + 3], h3v, az3); an3 = fmaf(wn[i + 3], h3v, an3);
        }
        float sr = (ar0 + ar1) + (ar2 + ar3);
        float sz = (az0 + az1) + (az2 + az3);
        float sn = (an0 + an1) + (an2 + an3);
#pragma unroll
        for (int off = 16; off; off >>= 1) {
            sr += __shfl_xor_sync(0xffffffffu, sr, off);
            sz += __shfl_xor_sync(0xffffffffu, sz, off);
            sn += __shfl_xor_sync(0xffffffffu, sn, off);
        }
        // activations (all lanes redundantly; lane0 stores)
        float gir = __shfl_sync(0xffffffffu, giv, 0);
        float giz = __shfl_sync(0xffffffffu, giv, 1);
        float gin = __shfl_sync(0xffffffffu, giv, 2);
        float r = 0.5f + 0.5f * tanhf(0.5f * (gir + sr + br));
        float z = 0.5f + 0.5f * tanhf(0.5f * (giz + sz + bz));
        float n = tanhf(fmaf(r, sn + bn, gin));
        float hn = fmaf(z, hprev - n, n);
        hprev = hn;
        if (lane == 0) g_ys[(size_t)t * HIDN + uu] = hn;

        __syncthreads();   // all 8 stores done (cumulative into release below)
        if (tid == 0)
            asm volatile("st.release.gpu.u32 [%0], %1;"
                         :: "l"(myflag), "r"((unsigned)(t + 1)) : "memory");
    }
}

// ---------------- Phase 3: logits = ys @ Wd + bd (unchanged) ----------------
__global__ __launch_bounds__(256)
void dense_kernel(const float* __restrict__ Wd, const float* __restrict__ bd,
                  float* __restrict__ out, int out_size)
{
    __shared__ float wd_s[HIDN * 9];
    const int tid = threadIdx.x;
    for (int i = tid; i < HIDN * 8; i += 256) wd_s[(i >> 3) * 9 + (i & 7)] = Wd[i];
    __syncthreads();
    const int warp = tid >> 5, lane = tid & 31;
    const int t = blockIdx.x * 8 + warp;
    const float* yrow = g_ys + (size_t)t * HIDN;
    float acc[8];
#pragma unroll
    for (int o = 0; o < 8; o++) acc[o] = 0.f;
#pragma unroll 4
    for (int i = 0; i < 32; i++) {
        int u = i * 32 + lane;
        float y = __ldg(yrow + u);
#pragma unroll
        for (int o = 0; o < 8; o++) acc[o] = fmaf(y, wd_s[u * 9 + o], acc[o]);
    }
#pragma unroll
    for (int o = 0; o < 8; o++) {
        float v = acc[o];
#pragma unroll
        for (int off = 16; off; off >>= 1) v += __shfl_xor_sync(0xffffffffu, v, off);
        int oi = t * 8 + o;
        if (lane == 0 && oi < out_size) out[oi] = v + bd[o];
    }
}

// ---------------- Phase 4: threefry (partitionable, verified) ---------------
__device__ __forceinline__ void tf2x32(unsigned k0, unsigned k1,
                                       unsigned x0, unsigned x1,
                                       unsigned& o0, unsigned& o1)
{
    unsigned k2 = k0 ^ k1 ^ 0x1BD11BDAu;
    x0 += k0; x1 += k1;
#define RND(r) x0 += x1; x1 = (x1 << (r)) | (x1 >> (32 - (r))); x1 ^= x0;
    RND(13) RND(15) RND(26) RND(6)
    x0 += k1; x1 += k2 + 1u;
    RND(17) RND(29) RND(16) RND(24)
    x0 += k2; x1 += k0 + 2u;
    RND(13) RND(15) RND(26) RND(6)
    x0 += k0; x1 += k1 + 3u;
    RND(17) RND(29) RND(16) RND(24)
    x0 += k1; x1 += k2 + 4u;
    RND(13) RND(15) RND(26) RND(6)
    x0 += k2; x1 += k0 + 5u;
#undef RND
    o0 = x0; o1 = x1;
}

__device__ __forceinline__ float gumbel_bits(unsigned b)
{
    float u = __uint_as_float((b >> 9) | 0x3f800000u) - 1.0f;
    u = fmaxf(u, 1.17549435e-38f);
    return -logf(-logf(u));
}

__global__ void action_kernel(const int* __restrict__ seedp,
                              float* __restrict__ out, int out_size)
{
    const int t = blockIdx.x * 256 + threadIdx.x;
    const unsigned sk0 = 0u, sk1 = (unsigned)seedp[0];
    unsigned ak0, ak1;
    tf2x32(sk0, sk1, 0u, 1u, ak0, ak1);          // act_rng = split(rng)[1]
    const unsigned i0 = 2u * (unsigned)t, i1 = i0 + 1u;
    unsigned b1, b2, c1, c2;
    tf2x32(ak0, ak1, 0u, i0, b1, b2);
    tf2x32(ak0, ak1, 0u, i1, c1, c2);
    const float s0 = gumbel_bits(b1 ^ b2) + out[(size_t)t * 8 + 0];
    const float s1 = gumbel_bits(c1 ^ c2) + out[(size_t)t * 8 + 1];
    int oi = 65536 + t;
    if (oi < out_size) out[oi] = (s1 > s0) ? 1.0f : 0.0f;
}

__global__ void finalh_kernel(float* __restrict__ out, int out_size)
{
    int i = threadIdx.x;
    int oi = 65536 + 8192 + i;
    if (oi < out_size) out[oi] = g_ys[(size_t)(T_STEPS - 1) * HIDN + i];
}

// ---------------------------------------------------------------------------
extern "C" void kernel_launch(void* const* d_in, const int* in_sizes, int n_in,
                              void* d_out, int out_size)
{
    const float* x  = (const float*)d_in[0];
    const float* h0 = (const float*)d_in[1];
    const float* Wi = (const float*)d_in[2];
    const float* Wh = (const float*)d_in[3];
    const float* bh = (const float*)d_in[4];
    const float* Wd = (const float*)d_in[5];
    const float* bd = (const float*)d_in[6];
    const int* seed = (const int*)d_in[7];
    float* out = (float*)d_out;

    reset_flags_kernel<<<16, 256>>>();
    sgemm_kernel<<<dim3(24, 64), 256>>>(x, Wi);
    gru_kernel<<<NCTA, GRU_THREADS>>>(h0, Wh, bh);
    dense_kernel<<<1024, 256>>>(Wd, bd, out, out_size);
    if (out_size > 65536) action_kernel<<<32, 256>>>(seed, out, out_size);
    if (out_size > 65536 + 8192) finalh_kernel<<<1, 1024>>>(out, out_size);
}